// round 15
// baseline (speedup 1.0000x reference)
#include <cuda_runtime.h>
#include <cuda_fp16.h>
#include <math.h>
#include <stdint.h>

#define Bsz 4
#define Tlen 1024
#define Dm 768
#define Nh 12
#define Fm 3072
#define Lc 12
#define Vv 50257
#define Rows (Bsz*Tlen)   /* 4096 */

// ---------------- scratch (static device globals; no allocation) ----------------
__device__ float g_x[Rows*Dm];                       // residual stream (fp32)
__device__ __half g_hhi[Rows*Dm], g_hlo[Rows*Dm];    // LN output hi/lo (f16)
__device__ __half g_qkvhi[Rows*3*Dm], g_qkvlo[Rows*3*Dm];  // qkv f16 hi/lo
__device__ __half g_ahi[Rows*Dm], g_alo[Rows*Dm];    // attn out hi/lo
__device__ __half g_fchi[Rows*Fm], g_fclo[Rows*Fm];  // gelu(fc) hi/lo
// transposed weights [N,K], single f16
__device__ __half w_qkv[Lc*3*Dm*Dm];
__device__ __half w_ap [Lc*Dm*Dm];
__device__ __half w_fc [Lc*Fm*Dm];
__device__ __half w_mp [Lc*Dm*Fm];
__device__ __half w_te [Vv*Dm];

// ---------------- helpers ----------------
__device__ __forceinline__ uint32_t smem_u32(const void* p) {
    uint32_t a;
    asm("{ .reg .u64 t; cvta.to.shared.u64 t, %1; cvt.u32.u64 %0, t; }" : "=r"(a) : "l"(p));
    return a;
}
#define SWZ(o) ((o) ^ ((((uint32_t)(o)) >> 3) & 0x70))

__device__ __forceinline__ void cpasync16(uint32_t s, const void* g, uint32_t sz) {
    asm volatile("cp.async.cg.shared.global [%0], [%1], 16, %2;\n"
                 :: "r"(s), "l"(g), "r"(sz) : "memory");
}
__device__ __forceinline__ void cpasync16f(uint32_t s, const void* g) {
    asm volatile("cp.async.cg.shared.global [%0], [%1], 16;\n"
                 :: "r"(s), "l"(g) : "memory");
}
__device__ __forceinline__ void cp_commit() {
    asm volatile("cp.async.commit_group;\n" ::: "memory");
}
__device__ __forceinline__ void cp_wait1() {
    asm volatile("cp.async.wait_group 1;\n" ::: "memory");
}
__device__ __forceinline__ void cp_wait0() {
    asm volatile("cp.async.wait_group 0;\n" ::: "memory");
}
__device__ __forceinline__ void ldsm4(uint32_t r[4], uint32_t addr) {
    asm volatile("ldmatrix.sync.aligned.m8n8.x4.shared.b16 {%0,%1,%2,%3}, [%4];"
                 : "=r"(r[0]), "=r"(r[1]), "=r"(r[2]), "=r"(r[3]) : "r"(addr));
}
__device__ __forceinline__ void ldsm4t(uint32_t r[4], uint32_t addr) {
    asm volatile("ldmatrix.sync.aligned.m8n8.x4.trans.shared.b16 {%0,%1,%2,%3}, [%4];"
                 : "=r"(r[0]), "=r"(r[1]), "=r"(r[2]), "=r"(r[3]) : "r"(addr));
}
__device__ __forceinline__ void mma16816(float c[4], const uint32_t a[4], const uint32_t b[2]) {
    asm volatile("mma.sync.aligned.m16n8k16.row.col.f32.f16.f16.f32 "
                 "{%0,%1,%2,%3}, {%4,%5,%6,%7}, {%8,%9}, {%0,%1,%2,%3};"
                 : "+f"(c[0]), "+f"(c[1]), "+f"(c[2]), "+f"(c[3])
                 : "r"(a[0]), "r"(a[1]), "r"(a[2]), "r"(a[3]), "r"(b[0]), "r"(b[1]));
}

// fast exp on the FMA pipe (no MUFU)
__device__ __forceinline__ float fexp(float x) {
    x = fmaxf(x, -80.f);
    float y = x * 1.4426950408889634f;
    float t = y + 12582912.f;
    int   bi = __float_as_int(t);
    float n = t - 12582912.f;
    float f = y - n;
    float p = 9.6181291e-3f;
    p = p * f + 5.5504109e-2f;
    p = p * f + 2.4022651e-1f;
    p = p * f + 6.9314718e-1f;
    p = p * f + 1.0f;
    float s = __int_as_float((bi + (127 - 0x400000)) << 23);
    return p * s;
}

// ---------------- embedding ----------------
__global__ void embed_kernel(const int* __restrict__ tokens,
                             const float* __restrict__ wte,
                             const float* __restrict__ wpe,
                             float* __restrict__ x) {
    int row = blockIdx.x;
    int t   = row % Tlen;
    int tok = tokens[row];
    const float* we = wte + (size_t)tok * Dm;
    const float* pe = wpe + (size_t)t   * Dm;
    float* xr = x + (size_t)row * Dm;
    for (int i = threadIdx.x; i < Dm; i += blockDim.x)
        xr[i] = we[i] + pe[i];
}

// ---------------- layernorm -> f16 hi/lo (warp per row, shuffle-only) ----------------
__global__ __launch_bounds__(256, 6) void ln_kernel(const float* __restrict__ x,
                          const float* __restrict__ g,
                          const float* __restrict__ b,
                          __half* __restrict__ ohi,
                          __half* __restrict__ olo) {
    const int warp = threadIdx.x >> 5, lane = threadIdx.x & 31;
    const int row  = blockIdx.x * 8 + warp;
    const float* xr = x + (size_t)row * Dm;

    float4 v[6];
    float s = 0.f, s2 = 0.f;
    #pragma unroll
    for (int i = 0; i < 6; i++) {
        v[i] = *(const float4*)(xr + lane * 4 + i * 128);
        s  += v[i].x + v[i].y + v[i].z + v[i].w;
        s2 += v[i].x * v[i].x + v[i].y * v[i].y + v[i].z * v[i].z + v[i].w * v[i].w;
    }
    #pragma unroll
    for (int o = 16; o > 0; o >>= 1) {
        s  += __shfl_xor_sync(0xffffffffu, s,  o);
        s2 += __shfl_xor_sync(0xffffffffu, s2, o);
    }
    float mean = s * (1.0f / Dm);
    float var  = s2 * (1.0f / Dm) - mean * mean;
    float rstd = rsqrtf(var + 1e-5f);

    size_t base = (size_t)row * Dm;
    #pragma unroll
    for (int i = 0; i < 6; i++) {
        int off = lane * 4 + i * 128;
        float4 gv = *(const float4*)(g + off);
        float4 bv = *(const float4*)(b + off);
        float o0 = (v[i].x - mean) * rstd * gv.x + bv.x;
        float o1 = (v[i].y - mean) * rstd * gv.y + bv.y;
        float o2 = (v[i].z - mean) * rstd * gv.z + bv.z;
        float o3 = (v[i].w - mean) * rstd * gv.w + bv.w;
        __half h0 = __float2half_rn(o0), h1 = __float2half_rn(o1);
        __half h2 = __float2half_rn(o2), h3 = __float2half_rn(o3);
        __half2 hA; hA.x = h0; hA.y = h1;
        __half2 hB; hB.x = h2; hB.y = h3;
        __half2 lA; lA.x = __float2half_rn(o0 - __half2float(h0));
                    lA.y = __float2half_rn(o1 - __half2float(h1));
        __half2 lB; lB.x = __float2half_rn(o2 - __half2float(h2));
                    lB.y = __float2half_rn(o3 - __half2float(h3));
        *reinterpret_cast<__half2*>(ohi + base + off)     = hA;
        *reinterpret_cast<__half2*>(ohi + base + off + 2) = hB;
        *reinterpret_cast<__half2*>(olo + base + off)     = lA;
        *reinterpret_cast<__half2*>(olo + base + off + 2) = lB;
    }
}

// ---------------- weight transpose + f16: W[K,N] -> out[N,K] ----------------
__global__ void wconvT_kernel(const float* __restrict__ W,
                              __half* __restrict__ hi,
                              int K, int N) {
    __shared__ float t[32][33];
    size_t zoff = (size_t)blockIdx.z * K * N;
    const float* Wl = W + zoff;
    int n0 = blockIdx.x * 32, k0 = blockIdx.y * 32;
    int tx = threadIdx.x, ty = threadIdx.y;
    for (int i = ty; i < 32; i += 8)
        t[i][tx] = Wl[(size_t)(k0 + i) * N + n0 + tx];
    __syncthreads();
    for (int i = ty; i < 32; i += 8) {
        float v = t[tx][i];
        hi[zoff + (size_t)(n0 + i) * K + k0 + tx] = __float2half_rn(v);
    }
}

__global__ void wte_conv_kernel(const float* __restrict__ W,
                                __half* __restrict__ hi, int n) {
    int i = blockIdx.x * 256 + threadIdx.x;
    if (i < n) hi[i] = __float2half_rn(W[i]);
}

// ---------------- HMMA GEMM (2-term f16 split): C = (Ahi+Alo)[M,K] @ B[N,K]^T ----------------
// MT=2,NT=4: 64x128 tile, 32KB/stage, 3 CTAs/SM (layer GEMMs).
// MT=4,NT=4: 128x128 tile, 48KB/stage, 2 CTAs/SM (lm_head).
// EPI: 1 = +bias+res -> fp32 | 2 = +bias,gelu -> f16 hi/lo | 3 = plain fp32 | 4 = +bias -> f16 hi/lo
#define GSMEM_MT4 98304
#define GSMEM_MT2 65536

template<int EPI, bool GUARD, int MT, int NT>
__global__ __launch_bounds__(256, (MT == 2 && NT == 4) ? 3 : 2) void mm_gemm(
    const __half* __restrict__ Ahi, const __half* __restrict__ Alo,
    const __half* __restrict__ B,
    const float* __restrict__ bias, const float* __restrict__ res,
    float* __restrict__ outF,
    __half* __restrict__ outHi, __half* __restrict__ outLo,
    int M, int N, int K)
{
    constexpr int CTAM   = MT * 32;
    constexpr int CTAN   = NT * 32;
    constexpr uint32_t AB = (uint32_t)CTAM * 128;
    constexpr uint32_t BB = (uint32_t)CTAN * 128;
    constexpr uint32_t STAGE = 2 * AB + BB;

    extern __shared__ char smem[];
    uint32_t sb = smem_u32(smem);
    const int m0 = blockIdx.x * CTAM;
    const int n0 = blockIdx.y * CTAN;
    const int tid  = threadIdx.x;
    const int warp = tid >> 5, lane = tid & 31;
    const int wm = warp >> 2, wn = warp & 3;

    float acc[MT][NT][4] = {};
    const int NC = K >> 6;

    auto issue = [&](int ch) {
        const uint32_t base = sb + (uint32_t)(ch & 1) * STAGE;
        const size_t koff = (size_t)ch * 64;
        #pragma unroll
        for (int c = 0; c < MT; c++) {
            int idx = tid + c * 256;
            int r = idx >> 3, g16 = idx & 7;
            size_t go = (size_t)(m0 + r) * K + koff + g16 * 8;
            uint32_t so = SWZ(r * 128 + g16 * 16);
            cpasync16f(base + so,      Ahi + go);
            cpasync16f(base + AB + so, Alo + go);
        }
        #pragma unroll
        for (int c = 0; c < NT; c++) {
            int idx = tid + c * 256;
            int r = idx >> 3, g16 = idx & 7;
            uint32_t so = SWZ(r * 128 + g16 * 16);
            if (GUARD) {
                int n = n0 + r;
                uint32_t ok = (n < N) ? 16u : 0u;
                cpasync16(base + 2 * AB + so,
                          B + (size_t)((n < N) ? n : 0) * K + koff + g16 * 8, ok);
            } else {
                cpasync16f(base + 2 * AB + so,
                           B + (size_t)(n0 + r) * K + koff + g16 * 8);
            }
        }
        cp_commit();
    };

    issue(0);
    for (int it = 0; it < NC; ++it) {
        if (it + 1 < NC) { issue(it + 1); cp_wait1(); }
        else             { cp_wait0(); }
        __syncthreads();

        const uint32_t aHi = sb + (uint32_t)(it & 1) * STAGE;
        const uint32_t aLo = aHi + AB;
        const uint32_t bBs = aHi + 2 * AB;
        #pragma unroll
        for (int ks = 0; ks < 4; ks++) {
            uint32_t ahi[MT][4], alo[MT][4], b[NT][2];
            #pragma unroll
            for (int mt = 0; mt < MT; mt++) {
                uint32_t so = SWZ((wm * (CTAM / 2) + mt * 16 + (lane & 15)) * 128 + ks * 32 + (lane >> 4) * 16);
                ldsm4(ahi[mt], aHi + so);
                ldsm4(alo[mt], aLo + so);
            }
            #pragma unroll
            for (int p = 0; p < NT / 2; p++) {
                int q = lane >> 3;
                uint32_t so = SWZ((wn * (NT * 8) + p * 16 + ((q >> 1) << 3) + (lane & 7)) * 128 + ks * 32 + (q & 1) * 16);
                uint32_t t4[4];
                ldsm4(t4, bBs + so);
                b[2 * p][0] = t4[0]; b[2 * p][1] = t4[1];
                b[2 * p + 1][0] = t4[2]; b[2 * p + 1][1] = t4[3];
            }
            #pragma unroll
            for (int mt = 0; mt < MT; mt++)
                #pragma unroll
                for (int nt = 0; nt < NT; nt++)
                    mma16816(acc[mt][nt], ahi[mt], b[nt]);
            #pragma unroll
            for (int mt = 0; mt < MT; mt++)
                #pragma unroll
                for (int nt = 0; nt < NT; nt++)
                    mma16816(acc[mt][nt], alo[mt], b[nt]);
        }
        __syncthreads();
    }

    const int g = lane >> 2, tig = lane & 3;
    #pragma unroll
    for (int mt = 0; mt < MT; mt++) {
        #pragma unroll
        for (int nt = 0; nt < NT; nt++) {
            int nc = n0 + wn * (NT * 8) + nt * 8 + tig * 2;
            #pragma unroll
            for (int h = 0; h < 2; h++) {
                int m = m0 + wm * (CTAM / 2) + mt * 16 + g + h * 8;
                float v0 = acc[mt][nt][2 * h];
                float v1 = acc[mt][nt][2 * h + 1];
                size_t gi = (size_t)m * N + nc;
                if (EPI == 3) {
                    if (!GUARD || nc < N)     outF[gi]     = v0;
                    if (!GUARD || nc + 1 < N) outF[gi + 1] = v1;
                } else {
                    v0 += bias[nc]; v1 += bias[nc + 1];
                    if (EPI == 2 || EPI == 4) {
                        if (EPI == 2) { v0 *= normcdff(v0); v1 *= normcdff(v1); }
                        __half h0 = __float2half_rn(v0);
                        __half h1 = __float2half_rn(v1);
                        __half2 hv; hv.x = h0; hv.y = h1;
                        __half2 lv;
                        lv.x = __float2half_rn(v0 - __half2float(h0));
                        lv.y = __float2half_rn(v1 - __half2float(h1));
                        *reinterpret_cast<__half2*>(outHi + gi) = hv;
                        *reinterpret_cast<__half2*>(outLo + gi) = lv;
                    } else {
                        if (EPI == 1) {
                            float2 r2 = *reinterpret_cast<const float2*>(res + gi);
                            v0 += r2.x; v1 += r2.y;
                        }
                        float2 o2; o2.x = v0; o2.y = v1;
                        *reinterpret_cast<float2*>(outF + gi) = o2;
                    }
                }
            }
        }
    }
}

// ---------------- flash attention: 64 queries/block, 4 warps, tensor-core ----------------
// smem: Qhi(8K) Qlo(8K) | 2 stages x [Khi Klo Vhi Vlo] (4x8K each)
#define FSMEM (16384 + 2*32768)

__global__ __launch_bounds__(128, 2) void fattn_kernel(
    const __half* __restrict__ qhi, const __half* __restrict__ qlo,
    __half* __restrict__ ohi, __half* __restrict__ olo)
{
    extern __shared__ char sm[];
    uint32_t sb = smem_u32(sm);
    const int qb = blockIdx.x, n = blockIdx.y, b = blockIdx.z;
    const int tid = threadIdx.x, lane = tid & 31, wq = tid >> 5;
    const int q0 = qb * 64;
    const size_t tb3 = (size_t)(b * Tlen) * (3 * Dm);
    const uint32_t QH = sb, QL = sb + 8192;

    // load Q hi/lo (rows are 128B contiguous at head offset)
    #pragma unroll
    for (int c = 0; c < 4; c++) {
        int idx = tid + c * 128;
        int r = idx >> 3, ch = idx & 7;
        size_t go = tb3 + (size_t)(q0 + r) * (3 * Dm) + n * 64 + ch * 8;
        uint32_t so = SWZ(r * 128 + ch * 16);
        cpasync16f(QH + so, qhi + go);
        cpasync16f(QL + so, qlo + go);
    }
    cp_commit();

    const int NTt = qb + 1;
    auto issueT = [&](int t) {
        uint32_t bs = sb + 16384 + (uint32_t)(t & 1) * 32768u;
        #pragma unroll
        for (int c = 0; c < 4; c++) {
            int idx = tid + c * 128;
            int r = idx >> 3, ch = idx & 7;
            size_t go = tb3 + (size_t)(t * 64 + r) * (3 * Dm) + n * 64 + ch * 8;
            uint32_t so = SWZ(r * 128 + ch * 16);
            cpasync16f(bs + so,         qhi + go + Dm);       // Khi
            cpasync16f(bs + 8192 + so,  qlo + go + Dm);       // Klo
            cpasync16f(bs + 16384 + so, qhi + go + 2 * Dm);   // Vhi
            cpasync16f(bs + 24576 + so, qlo + go + 2 * Dm);   // Vlo
        }
        cp_commit();
    };
    issueT(0);
    cp_wait0();
    __syncthreads();

    // Q a-frags, scaled by 1/8 (exact)
    uint32_t aQh[4][4], aQl[4][4];
    {
        const __half2 scv = __floats2half2_rn(0.125f, 0.125f);
        #pragma unroll
        for (int ks = 0; ks < 4; ks++) {
            uint32_t so = SWZ((wq * 16 + (lane & 15)) * 128 + ks * 32 + (lane >> 4) * 16);
            ldsm4(aQh[ks], QH + so);
            ldsm4(aQl[ks], QL + so);
            #pragma unroll
            for (int i = 0; i < 4; i++) {
                __half2 h = __hmul2(*reinterpret_cast<__half2*>(&aQh[ks][i]), scv);
                aQh[ks][i] = *reinterpret_cast<uint32_t*>(&h);
                __half2 l = __hmul2(*reinterpret_cast<__half2*>(&aQl[ks][i]), scv);
                aQl[ks][i] = *reinterpret_cast<uint32_t*>(&l);
            }
        }
    }

    float oacc[8][4] = {};
    float m0 = -1e30f, m1 = -1e30f, l0 = 0.f, l1 = 0.f;
    const int g = lane >> 2, tig = lane & 3;

    for (int t = 0; t < NTt; t++) {
        if (t + 1 < NTt) { issueT(t + 1); cp_wait1(); }
        else             { cp_wait0(); }
        __syncthreads();
        const uint32_t KH = sb + 16384 + (uint32_t)(t & 1) * 32768u;
        const uint32_t KL = KH + 8192, VH = KH + 16384, VL = KH + 24576;

        // ---- S = (Qhi+Qlo)(Khi)^T + Qhi(Klo)^T ----
        float sacc[8][4] = {};
        #pragma unroll
        for (int ks = 0; ks < 4; ks++) {
            uint32_t bh[8][2], bl[8][2];
            #pragma unroll
            for (int p = 0; p < 4; p++) {
                int qq = lane >> 3;
                uint32_t so = SWZ((p * 16 + ((qq >> 1) << 3) + (lane & 7)) * 128 + ks * 32 + (qq & 1) * 16);
                uint32_t t4[4];
                ldsm4(t4, KH + so);
                bh[2 * p][0] = t4[0]; bh[2 * p][1] = t4[1];
                bh[2 * p + 1][0] = t4[2]; bh[2 * p + 1][1] = t4[3];
                ldsm4(t4, KL + so);
                bl[2 * p][0] = t4[0]; bl[2 * p][1] = t4[1];
                bl[2 * p + 1][0] = t4[2]; bl[2 * p + 1][1] = t4[3];
            }
            #pragma unroll
            for (int nt = 0; nt < 8; nt++) {
                mma16816(sacc[nt], aQh[ks], bh[nt]);
                mma16816(sacc[nt], aQl[ks], bh[nt]);
                mma16816(sacc[nt], aQh[ks], bl[nt]);
            }
        }
        // causal mask (diagonal tile only)
        if (t == qb) {
            #pragma unroll
            for (int nt = 0; nt < 8; nt++)
                #pragma unroll
                for (int c = 0; c < 4; c++) {
                    int col = nt * 8 + 2 * tig + (c & 1);
                    int row = wq * 16 + g + ((c & 2) ? 8 : 0);
                    if (col > row) sacc[nt][c] = -1e30f;
                }
        }
        // ---- online softmax ----
        float mn0 = -1e30f, mn1 = -1e30f;
        #pragma unroll
        for (int nt = 0; nt < 8; nt++) {
            mn0 = fmaxf(mn0, fmaxf(sacc[nt][0], sacc[nt][1]));
            mn1 = fmaxf(mn1, fmaxf(sacc[nt][2], sacc[nt][3]));
        }
        mn0 = fmaxf(mn0, __shfl_xor_sync(0xffffffffu, mn0, 1));
        mn0 = fmaxf(mn0, __shfl_xor_sync(0xffffffffu, mn0, 2));
        mn1 = fmaxf(mn1, __shfl_xor_sync(0xffffffffu, mn1, 1));
        mn1 = fmaxf(mn1, __shfl_xor_sync(0xffffffffu, mn1, 2));
        float M0 = fmaxf(m0, mn0), M1 = fmaxf(m1, mn1);
        float a0 = fexp(m0 - M0), a1 = fexp(m1 - M1);
        m0 = M0; m1 = M1;
        float r0 = 0.f, r1 = 0.f;
        #pragma unroll
        for (int nt = 0; nt < 8; nt++) {
            sacc[nt][0] = fexp(sacc[nt][0] - M0);
            sacc[nt][1] = fexp(sacc[nt][1] - M0);
            sacc[nt][2] = fexp(sacc[nt][2] - M1);
            sacc[nt][3] = fexp(sacc[nt][3] - M1);
            r0 += sacc[nt][0] + sacc[nt][1];
            r1 += sacc[nt][2] + sacc[nt][3];
        }
        r0 += __shfl_xor_sync(0xffffffffu, r0, 1); r0 += __shfl_xor_sync(0xffffffffu, r0, 2);
        r1 += __shfl_xor_sync(0xffffffffu, r1, 1); r1 += __shfl_xor_sync(0xffffffffu, r1, 2);
        l0 = l0 * a0 + r0;
        l1 = l1 * a1 + r1;
        #pragma unroll
        for (int nt = 0; nt < 8; nt++) {
            oacc[nt][0] *= a0; oacc[nt][1] *= a0;
            oacc[nt][2] *= a1; oacc[nt][3] *= a1;
        }
        // ---- pack P c-frags -> a-frags (hi/lo), in-thread ----
        uint32_t pah[4][4], pal[4][4];
        #pragma unroll
        for (int ks = 0; ks < 4; ks++) {
            #pragma unroll
            for (int half_ = 0; half_ < 2; half_++) {       // ntA=2ks (regs 0,1), ntB=2ks+1 (regs 2,3)
                int nt = 2 * ks + half_;
                #pragma unroll
                for (int rr = 0; rr < 2; rr++) {            // rr=0: rows g; rr=1: rows g+8
                    float x0 = sacc[nt][2 * rr], x1 = sacc[nt][2 * rr + 1];
                    __half2 h = __floats2half2_rn(x0, x1);
                    pah[ks][half_ * 2 + rr] = *reinterpret_cast<uint32_t*>(&h);
                    __half2 l = __floats2half2_rn(x0 - __low2float(h), x1 - __high2float(h));
                    pal[ks][half_ * 2 + rr] = *reinterpret_cast<uint32_t*>(&l);
                }
            }
        }
        // ---- O += (Phi+Plo) Vhi + Phi Vlo ----
        #pragma unroll
        for (int ks = 0; ks < 4; ks++) {
            uint32_t vh[8][2], vl[8][2];
            #pragma unroll
            for (int p = 0; p < 4; p++) {
                uint32_t so = SWZ((16 * ks + (lane & 15)) * 128 + p * 32 + ((lane >> 4) << 4));
                uint32_t t4[4];
                ldsm4t(t4, VH + so);
                vh[2 * p][0] = t4[0]; vh[2 * p][1] = t4[1];
                vh[2 * p + 1][0] = t4[2]; vh[2 * p + 1][1] = t4[3];
                ldsm4t(t4, VL + so);
                vl[2 * p][0] = t4[0]; vl[2 * p][1] = t4[1];
                vl[2 * p + 1][0] = t4[2]; vl[2 * p + 1][1] = t4[3];
            }
            #pragma unroll
            for (int nt = 0; nt < 8; nt++) {
                mma16816(oacc[nt], pah[ks], vh[nt]);
                mma16816(oacc[nt], pal[ks], vh[nt]);
                mma16816(oacc[nt], pah[ks], vl[nt]);
            }
        }
        __syncthreads();   // all warps done with this stage before overwrite
    }

    // ---- finalize: O/l -> f16 hi/lo ----
    float il0 = 1.f / l0, il1 = 1.f / l1;
    #pragma unroll
    for (int nt = 0; nt < 8; nt++) {
        int col = n * 64 + nt * 8 + 2 * tig;
        size_t gi0 = (size_t)(b * Tlen + q0 + wq * 16 + g)     * Dm + col;
        size_t gi1 = (size_t)(b * Tlen + q0 + wq * 16 + g + 8) * Dm + col;
        float v0 = oacc[nt][0] * il0, v1 = oacc[nt][1] * il0;
        float v2 = oacc[nt][2] * il1, v3 = oacc[nt][3] * il1;
        __half2 h0 = __floats2half2_rn(v0, v1);
        __half2 h1 = __floats2half2_rn(v2, v3);
        __half2 l0v = __floats2half2_rn(v0 - __low2float(h0), v1 - __high2float(h0));
        __half2 l1v = __floats2half2_rn(v2 - __low2float(h1), v3 - __high2float(h1));
        *reinterpret_cast<__half2*>(ohi + gi0) = h0;
        *reinterpret_cast<__half2*>(olo + gi0) = l0v;
        *reinterpret_cast<__half2*>(ohi + gi1) = h1;
        *reinterpret_cast<__half2*>(olo + gi1) = l1v;
    }
}

// ---------------- host driver ----------------
extern "C" void kernel_launch(void* const* d_in, const int* in_sizes, int n_in,
                              void* d_out, int out_size) {
    const int*   tokens      = (const int*)  d_in[0];
    const float* wte         = (const float*)d_in[1];
    const float* wpe         = (const float*)d_in[2];
    const float* ln1_g       = (const float*)d_in[3];
    const float* ln1_b       = (const float*)d_in[4];
    const float* attn_w      = (const float*)d_in[5];
    const float* attn_b      = (const float*)d_in[6];
    const float* attn_proj_w = (const float*)d_in[7];
    const float* attn_proj_b = (const float*)d_in[8];
    const float* ln2_g       = (const float*)d_in[9];
    const float* ln2_b       = (const float*)d_in[10];
    const float* fc_w        = (const float*)d_in[11];
    const float* fc_b        = (const float*)d_in[12];
    const float* mlp_proj_w  = (const float*)d_in[13];
    const float* mlp_proj_b  = (const float*)d_in[14];
    const float* lnf_g       = (const float*)d_in[15];
    const float* lnf_b       = (const float*)d_in[16];
    float* out = (float*)d_out;

    float *xp;
    __half *hhi, *hlo, *qvh, *qvl, *ahi, *alo, *fchi, *fclo;
    __half *qw, *apw, *fcw, *mpw, *tew;
    cudaGetSymbolAddress((void**)&xp,   g_x);
    cudaGetSymbolAddress((void**)&hhi,  g_hhi);   cudaGetSymbolAddress((void**)&hlo,  g_hlo);
    cudaGetSymbolAddress((void**)&qvh,  g_qkvhi); cudaGetSymbolAddress((void**)&qvl,  g_qkvlo);
    cudaGetSymbolAddress((void**)&ahi,  g_ahi);   cudaGetSymbolAddress((void**)&alo,  g_alo);
    cudaGetSymbolAddress((void**)&fchi, g_fchi);  cudaGetSymbolAddress((void**)&fclo, g_fclo);
    cudaGetSymbolAddress((void**)&qw,  w_qkv);
    cudaGetSymbolAddress((void**)&apw, w_ap);
    cudaGetSymbolAddress((void**)&fcw, w_fc);
    cudaGetSymbolAddress((void**)&mpw, w_mp);
    cudaGetSymbolAddress((void**)&tew, w_te);

    cudaFuncSetAttribute((const void*)mm_gemm<4,false,2,4>, cudaFuncAttributeMaxDynamicSharedMemorySize, GSMEM_MT2);
    cudaFuncSetAttribute((const void*)mm_gemm<1,false,2,4>, cudaFuncAttributeMaxDynamicSharedMemorySize, GSMEM_MT2);
    cudaFuncSetAttribute((const void*)mm_gemm<2,false,2,4>, cudaFuncAttributeMaxDynamicSharedMemorySize, GSMEM_MT2);
    cudaFuncSetAttribute((const void*)mm_gemm<3,true ,4,4>, cudaFuncAttributeMaxDynamicSharedMemorySize, GSMEM_MT4);
    cudaFuncSetAttribute((const void*)fattn_kernel, cudaFuncAttributeMaxDynamicSharedMemorySize, FSMEM);

    const dim3 gQKV(Rows/64, (3*Dm)/128);
    const dim3 gP64(Rows/64, Dm/128);
    const dim3 gF  (Rows/64, Fm/128);
    const dim3 gV  (Rows/128, (Vv + 127)/128);
    const dim3 gAtt(Tlen/64, Nh, Bsz);
    dim3 wb(32, 8);

    wconvT_kernel<<<dim3(3*Dm/32, Dm/32, Lc), wb>>>(attn_w, qw, Dm, 3*Dm);        // 0
    embed_kernel<<<Rows, 256>>>(tokens, wte, wpe, xp);                             // 1
    ln_kernel<<<Rows/8, 256>>>(xp, ln1_g, ln1_b, hhi, hlo);                        // 2
    mm_gemm<4,false,2,4><<<gQKV, 256, GSMEM_MT2>>>(hhi, hlo, qw,                   // 3 <- ncu
        attn_b, nullptr, nullptr, qvh, qvl, Rows, 3*Dm, Dm);
    wconvT_kernel<<<dim3(Dm/32, Dm/32, Lc), wb>>>(attn_proj_w, apw, Dm, Dm);       // 4
    wconvT_kernel<<<dim3(Fm/32, Dm/32, Lc), wb>>>(fc_w, fcw, Dm, Fm);              // 5
    wconvT_kernel<<<dim3(Dm/32, Fm/32, Lc), wb>>>(mlp_proj_w, mpw, Fm, Dm);        // 6

    for (int l = 0; l < Lc; l++) {
        if (l > 0) {
            ln_kernel<<<Rows/8, 256>>>(xp, ln1_g + l*Dm, ln1_b + l*Dm, hhi, hlo);
            mm_gemm<4,false,2,4><<<gQKV, 256, GSMEM_MT2>>>(hhi, hlo,
                qw + (size_t)l*3*Dm*Dm,
                attn_b + (size_t)l*3*Dm, nullptr, nullptr, qvh, qvl,
                Rows, 3*Dm, Dm);
        }
        fattn_kernel<<<gAtt, 128, FSMEM>>>(qvh, qvl, ahi, alo);
        mm_gemm<1,false,2,4><<<gP64, 256, GSMEM_MT2>>>(ahi, alo,
            apw + (size_t)l*Dm*Dm,
            attn_proj_b + (size_t)l*Dm, xp, xp, nullptr, nullptr,
            Rows, Dm, Dm);
        ln_kernel<<<Rows/8, 256>>>(xp, ln2_g + l*Dm, ln2_b + l*Dm, hhi, hlo);
        mm_gemm<2,false,2,4><<<gF, 256, GSMEM_MT2>>>(hhi, hlo,
            fcw + (size_t)l*Fm*Dm,
            fc_b + (size_t)l*Fm, nullptr, nullptr, fchi, fclo,
            Rows, Fm, Dm);
        mm_gemm<1,false,2,4><<<gP64, 256, GSMEM_MT2>>>(fchi, fclo,
            mpw + (size_t)l*Dm*Fm,
            mlp_proj_b + (size_t)l*Dm, xp, xp, nullptr, nullptr,
            Rows, Dm, Fm);
    }

    wte_conv_kernel<<<(Vv*Dm + 255)/256, 256>>>(wte, tew, Vv*Dm);
    ln_kernel<<<Rows/8, 256>>>(xp, lnf_g, lnf_b, hhi, hlo);
    mm_gemm<3,true,4,4><<<gV, 256, GSMEM_MT4>>>(hhi, hlo, tew,
        nullptr, nullptr, out, nullptr, nullptr,
        Rows, Vv, Dm);
}

// round 17
// speedup vs baseline: 1.0063x; 1.0063x over previous
#include <cuda_runtime.h>
#include <cuda_fp16.h>
#include <math.h>
#include <stdint.h>

#define Bsz 4
#define Tlen 1024
#define Dm 768
#define Nh 12
#define Fm 3072
#define Lc 12
#define Vv 50257
#define Rows (Bsz*Tlen)   /* 4096 */

// ---------------- scratch (static device globals; no allocation) ----------------
__device__ float g_x[Rows*Dm];                       // residual stream (fp32)
__device__ __half g_hhi[Rows*Dm], g_hlo[Rows*Dm];    // LN output hi/lo (f16)
__device__ __half g_qkvhi[Rows*3*Dm], g_qkvlo[Rows*3*Dm];  // qkv f16 hi/lo
__device__ __half g_ahi[Rows*Dm], g_alo[Rows*Dm];    // attn out hi/lo
__device__ __half g_fchi[Rows*Fm], g_fclo[Rows*Fm];  // gelu(fc) hi/lo
// transposed weights [N,K], single f16
__device__ __half w_qkv[Lc*3*Dm*Dm];
__device__ __half w_ap [Lc*Dm*Dm];
__device__ __half w_fc [Lc*Fm*Dm];
__device__ __half w_mp [Lc*Dm*Fm];
__device__ __half w_te [Vv*Dm];

// ---------------- helpers ----------------
__device__ __forceinline__ uint32_t smem_u32(const void* p) {
    uint32_t a;
    asm("{ .reg .u64 t; cvta.to.shared.u64 t, %1; cvt.u32.u64 %0, t; }" : "=r"(a) : "l"(p));
    return a;
}
#define SWZ(o) ((o) ^ ((((uint32_t)(o)) >> 3) & 0x70))

__device__ __forceinline__ void cpasync16(uint32_t s, const void* g, uint32_t sz) {
    asm volatile("cp.async.cg.shared.global [%0], [%1], 16, %2;\n"
                 :: "r"(s), "l"(g), "r"(sz) : "memory");
}
__device__ __forceinline__ void cpasync16f(uint32_t s, const void* g) {
    asm volatile("cp.async.cg.shared.global [%0], [%1], 16;\n"
                 :: "r"(s), "l"(g) : "memory");
}
__device__ __forceinline__ void cp_commit() {
    asm volatile("cp.async.commit_group;\n" ::: "memory");
}
__device__ __forceinline__ void cp_wait1() {
    asm volatile("cp.async.wait_group 1;\n" ::: "memory");
}
__device__ __forceinline__ void cp_wait0() {
    asm volatile("cp.async.wait_group 0;\n" ::: "memory");
}
__device__ __forceinline__ void ldsm4(uint32_t r[4], uint32_t addr) {
    asm volatile("ldmatrix.sync.aligned.m8n8.x4.shared.b16 {%0,%1,%2,%3}, [%4];"
                 : "=r"(r[0]), "=r"(r[1]), "=r"(r[2]), "=r"(r[3]) : "r"(addr));
}
__device__ __forceinline__ void ldsm4t(uint32_t r[4], uint32_t addr) {
    asm volatile("ldmatrix.sync.aligned.m8n8.x4.trans.shared.b16 {%0,%1,%2,%3}, [%4];"
                 : "=r"(r[0]), "=r"(r[1]), "=r"(r[2]), "=r"(r[3]) : "r"(addr));
}
__device__ __forceinline__ void mma16816(float c[4], const uint32_t a[4], const uint32_t b[2]) {
    asm volatile("mma.sync.aligned.m16n8k16.row.col.f32.f16.f16.f32 "
                 "{%0,%1,%2,%3}, {%4,%5,%6,%7}, {%8,%9}, {%0,%1,%2,%3};"
                 : "+f"(c[0]), "+f"(c[1]), "+f"(c[2]), "+f"(c[3])
                 : "r"(a[0]), "r"(a[1]), "r"(a[2]), "r"(a[3]), "r"(b[0]), "r"(b[1]));
}

// fast exp on the FMA pipe (no MUFU)
__device__ __forceinline__ float fexp(float x) {
    x = fmaxf(x, -80.f);
    float y = x * 1.4426950408889634f;
    float t = y + 12582912.f;
    int   bi = __float_as_int(t);
    float n = t - 12582912.f;
    float f = y - n;
    float p = 9.6181291e-3f;
    p = p * f + 5.5504109e-2f;
    p = p * f + 2.4022651e-1f;
    p = p * f + 6.9314718e-1f;
    p = p * f + 1.0f;
    float s = __int_as_float((bi + (127 - 0x400000)) << 23);
    return p * s;
}

// ---------------- embedding ----------------
__global__ void embed_kernel(const int* __restrict__ tokens,
                             const float* __restrict__ wte,
                             const float* __restrict__ wpe,
                             float* __restrict__ x) {
    int row = blockIdx.x;
    int t   = row % Tlen;
    int tok = tokens[row];
    const float* we = wte + (size_t)tok * Dm;
    const float* pe = wpe + (size_t)t   * Dm;
    float* xr = x + (size_t)row * Dm;
    for (int i = threadIdx.x; i < Dm; i += blockDim.x)
        xr[i] = we[i] + pe[i];
}

// ---------------- layernorm -> f16 hi/lo (warp per row, shuffle-only) ----------------
__global__ __launch_bounds__(256, 6) void ln_kernel(const float* __restrict__ x,
                          const float* __restrict__ g,
                          const float* __restrict__ b,
                          __half* __restrict__ ohi,
                          __half* __restrict__ olo) {
    const int warp = threadIdx.x >> 5, lane = threadIdx.x & 31;
    const int row  = blockIdx.x * 8 + warp;
    const float* xr = x + (size_t)row * Dm;

    float4 v[6];
    float s = 0.f, s2 = 0.f;
    #pragma unroll
    for (int i = 0; i < 6; i++) {
        v[i] = *(const float4*)(xr + lane * 4 + i * 128);
        s  += v[i].x + v[i].y + v[i].z + v[i].w;
        s2 += v[i].x * v[i].x + v[i].y * v[i].y + v[i].z * v[i].z + v[i].w * v[i].w;
    }
    #pragma unroll
    for (int o = 16; o > 0; o >>= 1) {
        s  += __shfl_xor_sync(0xffffffffu, s,  o);
        s2 += __shfl_xor_sync(0xffffffffu, s2, o);
    }
    float mean = s * (1.0f / Dm);
    float var  = s2 * (1.0f / Dm) - mean * mean;
    float rstd = rsqrtf(var + 1e-5f);

    size_t base = (size_t)row * Dm;
    #pragma unroll
    for (int i = 0; i < 6; i++) {
        int off = lane * 4 + i * 128;
        float4 gv = *(const float4*)(g + off);
        float4 bv = *(const float4*)(b + off);
        float o0 = (v[i].x - mean) * rstd * gv.x + bv.x;
        float o1 = (v[i].y - mean) * rstd * gv.y + bv.y;
        float o2 = (v[i].z - mean) * rstd * gv.z + bv.z;
        float o3 = (v[i].w - mean) * rstd * gv.w + bv.w;
        __half h0 = __float2half_rn(o0), h1 = __float2half_rn(o1);
        __half h2 = __float2half_rn(o2), h3 = __float2half_rn(o3);
        __half2 hA; hA.x = h0; hA.y = h1;
        __half2 hB; hB.x = h2; hB.y = h3;
        __half2 lA; lA.x = __float2half_rn(o0 - __half2float(h0));
                    lA.y = __float2half_rn(o1 - __half2float(h1));
        __half2 lB; lB.x = __float2half_rn(o2 - __half2float(h2));
                    lB.y = __float2half_rn(o3 - __half2float(h3));
        *reinterpret_cast<__half2*>(ohi + base + off)     = hA;
        *reinterpret_cast<__half2*>(ohi + base + off + 2) = hB;
        *reinterpret_cast<__half2*>(olo + base + off)     = lA;
        *reinterpret_cast<__half2*>(olo + base + off + 2) = lB;
    }
}

// ---------------- weight transpose + f16: W[K,N] -> out[N,K] ----------------
__global__ void wconvT_kernel(const float* __restrict__ W,
                              __half* __restrict__ hi,
                              int K, int N) {
    __shared__ float t[32][33];
    size_t zoff = (size_t)blockIdx.z * K * N;
    const float* Wl = W + zoff;
    int n0 = blockIdx.x * 32, k0 = blockIdx.y * 32;
    int tx = threadIdx.x, ty = threadIdx.y;
    for (int i = ty; i < 32; i += 8)
        t[i][tx] = Wl[(size_t)(k0 + i) * N + n0 + tx];
    __syncthreads();
    for (int i = ty; i < 32; i += 8) {
        float v = t[tx][i];
        hi[zoff + (size_t)(n0 + i) * K + k0 + tx] = __float2half_rn(v);
    }
}

__global__ void wte_conv_kernel(const float* __restrict__ W,
                                __half* __restrict__ hi, int n) {
    int i = blockIdx.x * 256 + threadIdx.x;
    if (i < n) hi[i] = __float2half_rn(W[i]);
}

// ---------------- HMMA GEMM (2-term f16 split): C = (Ahi+Alo)[M,K] @ B[N,K]^T ----------------
// MT=2,NT=4: 64x128 tile, 32KB/stage. EPI 1/3: 3 CTAs/SM (85 regs ok).
// EPI 2/4 (hi/lo epilogues need more temps): 2 CTAs/SM to avoid spills.
// MT=4,NT=4: 128x128 tile, 48KB/stage, 2 CTAs/SM (lm_head).
// EPI: 1 = +bias+res -> fp32 | 2 = +bias,gelu -> f16 hi/lo | 3 = plain fp32 | 4 = +bias -> f16 hi/lo
#define GSMEM_MT4 98304
#define GSMEM_MT2 65536

template<int EPI, bool GUARD, int MT, int NT>
__global__ __launch_bounds__(256, (MT == 2 && NT == 4 && EPI != 2 && EPI != 4) ? 3 : 2) void mm_gemm(
    const __half* __restrict__ Ahi, const __half* __restrict__ Alo,
    const __half* __restrict__ B,
    const float* __restrict__ bias, const float* __restrict__ res,
    float* __restrict__ outF,
    __half* __restrict__ outHi, __half* __restrict__ outLo,
    int M, int N, int K)
{
    constexpr int CTAM   = MT * 32;
    constexpr int CTAN   = NT * 32;
    constexpr uint32_t AB = (uint32_t)CTAM * 128;
    constexpr uint32_t BB = (uint32_t)CTAN * 128;
    constexpr uint32_t STAGE = 2 * AB + BB;

    extern __shared__ char smem[];
    uint32_t sb = smem_u32(smem);
    const int m0 = blockIdx.x * CTAM;
    const int n0 = blockIdx.y * CTAN;
    const int tid  = threadIdx.x;
    const int warp = tid >> 5, lane = tid & 31;
    const int wm = warp >> 2, wn = warp & 3;

    float acc[MT][NT][4] = {};
    const int NC = K >> 6;

    auto issue = [&](int ch) {
        const uint32_t base = sb + (uint32_t)(ch & 1) * STAGE;
        const size_t koff = (size_t)ch * 64;
        #pragma unroll
        for (int c = 0; c < MT; c++) {
            int idx = tid + c * 256;
            int r = idx >> 3, g16 = idx & 7;
            size_t go = (size_t)(m0 + r) * K + koff + g16 * 8;
            uint32_t so = SWZ(r * 128 + g16 * 16);
            cpasync16f(base + so,      Ahi + go);
            cpasync16f(base + AB + so, Alo + go);
        }
        #pragma unroll
        for (int c = 0; c < NT; c++) {
            int idx = tid + c * 256;
            int r = idx >> 3, g16 = idx & 7;
            uint32_t so = SWZ(r * 128 + g16 * 16);
            if (GUARD) {
                int n = n0 + r;
                uint32_t ok = (n < N) ? 16u : 0u;
                cpasync16(base + 2 * AB + so,
                          B + (size_t)((n < N) ? n : 0) * K + koff + g16 * 8, ok);
            } else {
                cpasync16f(base + 2 * AB + so,
                           B + (size_t)(n0 + r) * K + koff + g16 * 8);
            }
        }
        cp_commit();
    };

    issue(0);
    for (int it = 0; it < NC; ++it) {
        if (it + 1 < NC) { issue(it + 1); cp_wait1(); }
        else             { cp_wait0(); }
        __syncthreads();

        const uint32_t aHi = sb + (uint32_t)(it & 1) * STAGE;
        const uint32_t aLo = aHi + AB;
        const uint32_t bBs = aHi + 2 * AB;
        #pragma unroll
        for (int ks = 0; ks < 4; ks++) {
            uint32_t ahi[MT][4], alo[MT][4], b[NT][2];
            #pragma unroll
            for (int mt = 0; mt < MT; mt++) {
                uint32_t so = SWZ((wm * (CTAM / 2) + mt * 16 + (lane & 15)) * 128 + ks * 32 + (lane >> 4) * 16);
                ldsm4(ahi[mt], aHi + so);
                ldsm4(alo[mt], aLo + so);
            }
            #pragma unroll
            for (int p = 0; p < NT / 2; p++) {
                int q = lane >> 3;
                uint32_t so = SWZ((wn * (NT * 8) + p * 16 + ((q >> 1) << 3) + (lane & 7)) * 128 + ks * 32 + (q & 1) * 16);
                uint32_t t4[4];
                ldsm4(t4, bBs + so);
                b[2 * p][0] = t4[0]; b[2 * p][1] = t4[1];
                b[2 * p + 1][0] = t4[2]; b[2 * p + 1][1] = t4[3];
            }
            #pragma unroll
            for (int mt = 0; mt < MT; mt++)
                #pragma unroll
                for (int nt = 0; nt < NT; nt++)
                    mma16816(acc[mt][nt], ahi[mt], b[nt]);
            #pragma unroll
            for (int mt = 0; mt < MT; mt++)
                #pragma unroll
                for (int nt = 0; nt < NT; nt++)
                    mma16816(acc[mt][nt], alo[mt], b[nt]);
        }
        __syncthreads();
    }

    const int g = lane >> 2, tig = lane & 3;
    #pragma unroll
    for (int mt = 0; mt < MT; mt++) {
        #pragma unroll
        for (int nt = 0; nt < NT; nt++) {
            int nc = n0 + wn * (NT * 8) + nt * 8 + tig * 2;
            #pragma unroll
            for (int h = 0; h < 2; h++) {
                int m = m0 + wm * (CTAM / 2) + mt * 16 + g + h * 8;
                float v0 = acc[mt][nt][2 * h];
                float v1 = acc[mt][nt][2 * h + 1];
                size_t gi = (size_t)m * N + nc;
                if (EPI == 3) {
                    if (!GUARD || nc < N)     outF[gi]     = v0;
                    if (!GUARD || nc + 1 < N) outF[gi + 1] = v1;
                } else {
                    v0 += bias[nc]; v1 += bias[nc + 1];
                    if (EPI == 2 || EPI == 4) {
                        if (EPI == 2) { v0 *= normcdff(v0); v1 *= normcdff(v1); }
                        __half h0 = __float2half_rn(v0);
                        __half h1 = __float2half_rn(v1);
                        __half2 hv; hv.x = h0; hv.y = h1;
                        __half2 lv;
                        lv.x = __float2half_rn(v0 - __half2float(h0));
                        lv.y = __float2half_rn(v1 - __half2float(h1));
                        *reinterpret_cast<__half2*>(outHi + gi) = hv;
                        *reinterpret_cast<__half2*>(outLo + gi) = lv;
                    } else {
                        if (EPI == 1) {
                            float2 r2 = *reinterpret_cast<const float2*>(res + gi);
                            v0 += r2.x; v1 += r2.y;
                        }
                        float2 o2; o2.x = v0; o2.y = v1;
                        *reinterpret_cast<float2*>(outF + gi) = o2;
                    }
                }
            }
        }
    }
}

// ---------------- flash attention: 64 queries/block, 4 warps, tensor-core ----------------
// smem: Qhi(8K) Qlo(8K) | 2 stages x [Khi Klo Vhi Vlo] (4x8K each)
#define FSMEM (16384 + 2*32768)

__global__ __launch_bounds__(128, 2) void fattn_kernel(
    const __half* __restrict__ qhi, const __half* __restrict__ qlo,
    __half* __restrict__ ohi, __half* __restrict__ olo)
{
    extern __shared__ char sm[];
    uint32_t sb = smem_u32(sm);
    const int qb = gridDim.x - 1 - blockIdx.x;   // heavy blocks first
    const int n = blockIdx.y, b = blockIdx.z;
    const int tid = threadIdx.x, lane = tid & 31, wq = tid >> 5;
    const int q0 = qb * 64;
    const size_t tb3 = (size_t)(b * Tlen) * (3 * Dm);
    const uint32_t QH = sb, QL = sb + 8192;

    #pragma unroll
    for (int c = 0; c < 4; c++) {
        int idx = tid + c * 128;
        int r = idx >> 3, ch = idx & 7;
        size_t go = tb3 + (size_t)(q0 + r) * (3 * Dm) + n * 64 + ch * 8;
        uint32_t so = SWZ(r * 128 + ch * 16);
        cpasync16f(QH + so, qhi + go);
        cpasync16f(QL + so, qlo + go);
    }
    cp_commit();

    const int NTt = qb + 1;
    auto issueT = [&](int t) {
        uint32_t bs = sb + 16384 + (uint32_t)(t & 1) * 32768u;
        #pragma unroll
        for (int c = 0; c < 4; c++) {
            int idx = tid + c * 128;
            int r = idx >> 3, ch = idx & 7;
            size_t go = tb3 + (size_t)(t * 64 + r) * (3 * Dm) + n * 64 + ch * 8;
            uint32_t so = SWZ(r * 128 + ch * 16);
            cpasync16f(bs + so,         qhi + go + Dm);       // Khi
            cpasync16f(bs + 8192 + so,  qlo + go + Dm);       // Klo
            cpasync16f(bs + 16384 + so, qhi + go + 2 * Dm);   // Vhi
            cpasync16f(bs + 24576 + so, qlo + go + 2 * Dm);   // Vlo
        }
        cp_commit();
    };
    issueT(0);
    cp_wait0();
    __syncthreads();

    uint32_t aQh[4][4], aQl[4][4];
    {
        const __half2 scv = __floats2half2_rn(0.125f, 0.125f);
        #pragma unroll
        for (int ks = 0; ks < 4; ks++) {
            uint32_t so = SWZ((wq * 16 + (lane & 15)) * 128 + ks * 32 + (lane >> 4) * 16);
            ldsm4(aQh[ks], QH + so);
            ldsm4(aQl[ks], QL + so);
            #pragma unroll
            for (int i = 0; i < 4; i++) {
                __half2 h = __hmul2(*reinterpret_cast<__half2*>(&aQh[ks][i]), scv);
                aQh[ks][i] = *reinterpret_cast<uint32_t*>(&h);
                __half2 l = __hmul2(*reinterpret_cast<__half2*>(&aQl[ks][i]), scv);
                aQl[ks][i] = *reinterpret_cast<uint32_t*>(&l);
            }
        }
    }

    float oacc[8][4] = {};
    float m0 = -1e30f, m1 = -1e30f, l0 = 0.f, l1 = 0.f;
    const int g = lane >> 2, tig = lane & 3;

    for (int t = 0; t < NTt; t++) {
        if (t + 1 < NTt) { issueT(t + 1); cp_wait1(); }
        else             { cp_wait0(); }
        __syncthreads();
        const uint32_t KH = sb + 16384 + (uint32_t)(t & 1) * 32768u;
        const uint32_t KL = KH + 8192, VH = KH + 16384, VL = KH + 24576;

        // ---- S = (Qhi+Qlo)(Khi)^T + Qhi(Klo)^T  [term-major: 8 indep acc between reuse] ----
        float sacc[8][4] = {};
        #pragma unroll
        for (int ks = 0; ks < 4; ks++) {
            uint32_t bh[8][2], bl[8][2];
            #pragma unroll
            for (int p = 0; p < 4; p++) {
                int qq = lane >> 3;
                uint32_t so = SWZ((p * 16 + ((qq >> 1) << 3) + (lane & 7)) * 128 + ks * 32 + (qq & 1) * 16);
                uint32_t t4[4];
                ldsm4(t4, KH + so);
                bh[2 * p][0] = t4[0]; bh[2 * p][1] = t4[1];
                bh[2 * p + 1][0] = t4[2]; bh[2 * p + 1][1] = t4[3];
                ldsm4(t4, KL + so);
                bl[2 * p][0] = t4[0]; bl[2 * p][1] = t4[1];
                bl[2 * p + 1][0] = t4[2]; bl[2 * p + 1][1] = t4[3];
            }
            #pragma unroll
            for (int nt = 0; nt < 8; nt++) mma16816(sacc[nt], aQh[ks], bh[nt]);
            #pragma unroll
            for (int nt = 0; nt < 8; nt++) mma16816(sacc[nt], aQl[ks], bh[nt]);
            #pragma unroll
            for (int nt = 0; nt < 8; nt++) mma16816(sacc[nt], aQh[ks], bl[nt]);
        }
        if (t == qb) {
            #pragma unroll
            for (int nt = 0; nt < 8; nt++)
                #pragma unroll
                for (int c = 0; c < 4; c++) {
                    int col = nt * 8 + 2 * tig + (c & 1);
                    int row = wq * 16 + g + ((c & 2) ? 8 : 0);
                    if (col > row) sacc[nt][c] = -1e30f;
                }
        }
        // ---- online softmax ----
        float mn0 = -1e30f, mn1 = -1e30f;
        #pragma unroll
        for (int nt = 0; nt < 8; nt++) {
            mn0 = fmaxf(mn0, fmaxf(sacc[nt][0], sacc[nt][1]));
            mn1 = fmaxf(mn1, fmaxf(sacc[nt][2], sacc[nt][3]));
        }
        mn0 = fmaxf(mn0, __shfl_xor_sync(0xffffffffu, mn0, 1));
        mn0 = fmaxf(mn0, __shfl_xor_sync(0xffffffffu, mn0, 2));
        mn1 = fmaxf(mn1, __shfl_xor_sync(0xffffffffu, mn1, 1));
        mn1 = fmaxf(mn1, __shfl_xor_sync(0xffffffffu, mn1, 2));
        float M0 = fmaxf(m0, mn0), M1 = fmaxf(m1, mn1);
        float a0 = fexp(m0 - M0), a1 = fexp(m1 - M1);
        m0 = M0; m1 = M1;
        float r0 = 0.f, r1 = 0.f;
        #pragma unroll
        for (int nt = 0; nt < 8; nt++) {
            sacc[nt][0] = fexp(sacc[nt][0] - M0);
            sacc[nt][1] = fexp(sacc[nt][1] - M0);
            sacc[nt][2] = fexp(sacc[nt][2] - M1);
            sacc[nt][3] = fexp(sacc[nt][3] - M1);
            r0 += sacc[nt][0] + sacc[nt][1];
            r1 += sacc[nt][2] + sacc[nt][3];
        }
        r0 += __shfl_xor_sync(0xffffffffu, r0, 1); r0 += __shfl_xor_sync(0xffffffffu, r0, 2);
        r1 += __shfl_xor_sync(0xffffffffu, r1, 1); r1 += __shfl_xor_sync(0xffffffffu, r1, 2);
        l0 = l0 * a0 + r0;
        l1 = l1 * a1 + r1;
        #pragma unroll
        for (int nt = 0; nt < 8; nt++) {
            oacc[nt][0] *= a0; oacc[nt][1] *= a0;
            oacc[nt][2] *= a1; oacc[nt][3] *= a1;
        }
        // ---- pack P c-frags -> a-frags (hi/lo) ----
        uint32_t pah[4][4], pal[4][4];
        #pragma unroll
        for (int ks = 0; ks < 4; ks++) {
            #pragma unroll
            for (int half_ = 0; half_ < 2; half_++) {
                int nt = 2 * ks + half_;
                #pragma unroll
                for (int rr = 0; rr < 2; rr++) {
                    float x0 = sacc[nt][2 * rr], x1 = sacc[nt][2 * rr + 1];
                    __half2 h = __floats2half2_rn(x0, x1);
                    pah[ks][half_ * 2 + rr] = *reinterpret_cast<uint32_t*>(&h);
                    __half2 l = __floats2half2_rn(x0 - __low2float(h), x1 - __high2float(h));
                    pal[ks][half_ * 2 + rr] = *reinterpret_cast<uint32_t*>(&l);
                }
            }
        }
        // ---- O += (Phi+Plo) Vhi + Phi Vlo  [term-major] ----
        #pragma unroll
        for (int ks = 0; ks < 4; ks++) {
            uint32_t vh[8][2], vl[8][2];
            #pragma unroll
            for (int p = 0; p < 4; p++) {
                uint32_t so = SWZ((16 * ks + (lane & 15)) * 128 + p * 32 + ((lane >> 4) << 4));
                uint32_t t4[4];
                ldsm4t(t4, VH + so);
                vh[2 * p][0] = t4[0]; vh[2 * p][1] = t4[1];
                vh[2 * p + 1][0] = t4[2]; vh[2 * p + 1][1] = t4[3];
                ldsm4t(t4, VL + so);
                vl[2 * p][0] = t4[0]; vl[2 * p][1] = t4[1];
                vl[2 * p + 1][0] = t4[2]; vl[2 * p + 1][1] = t4[3];
            }
            #pragma unroll
            for (int nt = 0; nt < 8; nt++) mma16816(oacc[nt], pah[ks], vh[nt]);
            #pragma unroll
            for (int nt = 0; nt < 8; nt++) mma16816(oacc[nt], pal[ks], vh[nt]);
            #pragma unroll
            for (int nt = 0; nt < 8; nt++) mma16816(oacc[nt], pah[ks], vl[nt]);
        }
        __syncthreads();
    }

    float il0 = 1.f / l0, il1 = 1.f / l1;
    #pragma unroll
    for (int nt = 0; nt < 8; nt++) {
        int col = n * 64 + nt * 8 + 2 * tig;
        size_t gi0 = (size_t)(b * Tlen + q0 + wq * 16 + g)     * Dm + col;
        size_t gi1 = (size_t)(b * Tlen + q0 + wq * 16 + g + 8) * Dm + col;
        float v0 = oacc[nt][0] * il0, v1 = oacc[nt][1] * il0;
        float v2 = oacc[nt][2] * il1, v3 = oacc[nt][3] * il1;
        __half2 h0 = __floats2half2_rn(v0, v1);
        __half2 h1 = __floats2half2_rn(v2, v3);
        __half2 l0v = __floats2half2_rn(v0 - __low2float(h0), v1 - __high2float(h0));
        __half2 l1v = __floats2half2_rn(v2 - __low2float(h1), v3 - __high2float(h1));
        *reinterpret_cast<__half2*>(ohi + gi0) = h0;
        *reinterpret_cast<__half2*>(olo + gi0) = l0v;
        *reinterpret_cast<__half2*>(ohi + gi1) = h1;
        *reinterpret_cast<__half2*>(olo + gi1) = l1v;
    }
}

// ---------------- host driver ----------------
extern "C" void kernel_launch(void* const* d_in, const int* in_sizes, int n_in,
                              void* d_out, int out_size) {
    const int*   tokens      = (const int*)  d_in[0];
    const float* wte         = (const float*)d_in[1];
    const float* wpe         = (const float*)d_in[2];
    const float* ln1_g       = (const float*)d_in[3];
    const float* ln1_b       = (const float*)d_in[4];
    const float* attn_w      = (const float*)d_in[5];
    const float* attn_b      = (const float*)d_in[6];
    const float* attn_proj_w = (const float*)d_in[7];
    const float* attn_proj_b = (const float*)d_in[8];
    const float* ln2_g       = (const float*)d_in[9];
    const float* ln2_b       = (const float*)d_in[10];
    const float* fc_w        = (const float*)d_in[11];
    const float* fc_b        = (const float*)d_in[12];
    const float* mlp_proj_w  = (const float*)d_in[13];
    const float* mlp_proj_b  = (const float*)d_in[14];
    const float* lnf_g       = (const float*)d_in[15];
    const float* lnf_b       = (const float*)d_in[16];
    float* out = (float*)d_out;

    float *xp;
    __half *hhi, *hlo, *qvh, *qvl, *ahi, *alo, *fchi, *fclo;
    __half *qw, *apw, *fcw, *mpw, *tew;
    cudaGetSymbolAddress((void**)&xp,   g_x);
    cudaGetSymbolAddress((void**)&hhi,  g_hhi);   cudaGetSymbolAddress((void**)&hlo,  g_hlo);
    cudaGetSymbolAddress((void**)&qvh,  g_qkvhi); cudaGetSymbolAddress((void**)&qvl,  g_qkvlo);
    cudaGetSymbolAddress((void**)&ahi,  g_ahi);   cudaGetSymbolAddress((void**)&alo,  g_alo);
    cudaGetSymbolAddress((void**)&fchi, g_fchi);  cudaGetSymbolAddress((void**)&fclo, g_fclo);
    cudaGetSymbolAddress((void**)&qw,  w_qkv);
    cudaGetSymbolAddress((void**)&apw, w_ap);
    cudaGetSymbolAddress((void**)&fcw, w_fc);
    cudaGetSymbolAddress((void**)&mpw, w_mp);
    cudaGetSymbolAddress((void**)&tew, w_te);

    cudaFuncSetAttribute((const void*)mm_gemm<4,false,2,4>, cudaFuncAttributeMaxDynamicSharedMemorySize, GSMEM_MT2);
    cudaFuncSetAttribute((const void*)mm_gemm<1,false,2,4>, cudaFuncAttributeMaxDynamicSharedMemorySize, GSMEM_MT2);
    cudaFuncSetAttribute((const void*)mm_gemm<2,false,2,4>, cudaFuncAttributeMaxDynamicSharedMemorySize, GSMEM_MT2);
    cudaFuncSetAttribute((const void*)mm_gemm<3,true ,4,4>, cudaFuncAttributeMaxDynamicSharedMemorySize, GSMEM_MT4);
    cudaFuncSetAttribute((const void*)fattn_kernel, cudaFuncAttributeMaxDynamicSharedMemorySize, FSMEM);

    const dim3 gQKV(Rows/64, (3*Dm)/128);
    const dim3 gP64(Rows/64, Dm/128);
    const dim3 gF  (Rows/64, Fm/128);
    const dim3 gV  (Rows/128, (Vv + 127)/128);
    const dim3 gAtt(Tlen/64, Nh, Bsz);
    dim3 wb(32, 8);

    wconvT_kernel<<<dim3(3*Dm/32, Dm/32, Lc), wb>>>(attn_w, qw, Dm, 3*Dm);        // 0
    embed_kernel<<<Rows, 256>>>(tokens, wte, wpe, xp);                             // 1
    ln_kernel<<<Rows/8, 256>>>(xp, ln1_g, ln1_b, hhi, hlo);                        // 2
    mm_gemm<4,false,2,4><<<gQKV, 256, GSMEM_MT2>>>(hhi, hlo, qw,                   // 3 <- ncu
        attn_b, nullptr, nullptr, qvh, qvl, Rows, 3*Dm, Dm);
    wconvT_kernel<<<dim3(Dm/32, Dm/32, Lc), wb>>>(attn_proj_w, apw, Dm, Dm);       // 4
    wconvT_kernel<<<dim3(Fm/32, Dm/32, Lc), wb>>>(fc_w, fcw, Dm, Fm);              // 5
    wconvT_kernel<<<dim3(Dm/32, Fm/32, Lc), wb>>>(mlp_proj_w, mpw, Fm, Dm);        // 6

    for (int l = 0; l < Lc; l++) {
        if (l > 0) {
            ln_kernel<<<Rows/8, 256>>>(xp, ln1_g + l*Dm, ln1_b + l*Dm, hhi, hlo);
            mm_gemm<4,false,2,4><<<gQKV, 256, GSMEM_MT2>>>(hhi, hlo,
                qw + (size_t)l*3*Dm*Dm,
                attn_b + (size_t)l*3*Dm, nullptr, nullptr, qvh, qvl,
                Rows, 3*Dm, Dm);
        }
        fattn_kernel<<<gAtt, 128, FSMEM>>>(qvh, qvl, ahi, alo);
        mm_gemm<1,false,2,4><<<gP64, 256, GSMEM_MT2>>>(ahi, alo,
            apw + (size_t)l*Dm*Dm,
            attn_proj_b + (size_t)l*Dm, xp, xp, nullptr, nullptr,
            Rows, Dm, Dm);
        ln_kernel<<<Rows/8, 256>>>(xp, ln2_g + l*Dm, ln2_b + l*Dm, hhi, hlo);
        mm_gemm<2,false,2,4><<<gF, 256, GSMEM_MT2>>>(hhi, hlo,
            fcw + (size_t)l*Fm*Dm,
            fc_b + (size_t)l*Fm, nullptr, nullptr, fchi, fclo,
            Rows, Fm, Dm);
        mm_gemm<1,false,2,4><<<gP64, 256, GSMEM_MT2>>>(fchi, fclo,
            mpw + (size_t)l*Dm*Fm,
            mlp_proj_b + (size_t)l*Dm, xp, xp, nullptr, nullptr,
            Rows, Dm, Fm);
    }

    wte_conv_kernel<<<(Vv*Dm + 255)/256, 256>>>(wte, tew, Vv*Dm);
    ln_kernel<<<Rows/8, 256>>>(xp, lnf_g, lnf_b, hhi, hlo);
    mm_gemm<3,true,4,4><<<gV, 256, GSMEM_MT4>>>(hhi, hlo, tew,
        nullptr, nullptr, out, nullptr, nullptr,
        Rows, Vv, Dm);
}